// round 9
// baseline (speedup 1.0000x reference)
#include <cuda_runtime.h>
#include <stdint.h>
#include <stddef.h>

// Problem constants (ReinforceDistributed): B=8192, HALL=4096, C=3, EPS=10
#define B_TOT    8192
#define H_ALL    4096
#define N_E      10
#define E_STRIDE 33554432u     // 8192 * 4096 = 2^25
#define TPB      256
#define N_ITER   (H_ALL / TPB) // 16
#define NEG_BIG  (-3.0e38f)

// ---------------------------------------------------------------------------
// JAX threefry2x32, key (0, 42), partitionable path (CONFIRMED by R8 readout):
//   bits[i] = out0 ^ out1 of block (c0=0, c1=i)
// ks0 = 0, ks1 = 42, ks2 = 0x1BD11BDA ^ 0 ^ 42 = 0x1BD11BF0
// ---------------------------------------------------------------------------
static __device__ __forceinline__ uint32_t rotl32(uint32_t x, uint32_t r) {
    return __funnelshift_l(x, x, r);
}

static __device__ __forceinline__ uint32_t tf2x32_xor(uint32_t cnt) {
    const uint32_t ks1 = 42u;
    const uint32_t ks2 = 0x1BD11BF0u;
    uint32_t x0 = 0u;          // counts_hi (0) + ks0 (0)
    uint32_t x1 = cnt + ks1;   // counts_lo + ks1
#define TFR(r) { x0 += x1; x1 = rotl32(x1, (r)); x1 ^= x0; }
    TFR(13) TFR(15) TFR(26) TFR(6)
    x0 += ks1; x1 += ks2 + 1u;
    TFR(17) TFR(29) TFR(16) TFR(24)
    x0 += ks2; x1 += 2u;                 // + ks0(0) + 2
    TFR(13) TFR(15) TFR(26) TFR(6)
    /* x0 += ks0 (0) */ x1 += ks1 + 3u;
    TFR(17) TFR(29) TFR(16) TFR(24)
    x0 += ks1; x1 += ks2 + 4u;
    TFR(13) TFR(15) TFR(26) TFR(6)
    x0 += ks2; x1 += 5u;                 // + ks0(0) + 5
#undef TFR
    return x0 ^ x1;
}

// order-preserving float<->uint map (total order on IEEE floats)
static __device__ __forceinline__ uint32_t fmap(float f) {
    uint32_t u = __float_as_uint(f);
    return (u & 0x80000000u) ? ~u : (u | 0x80000000u);
}
static __device__ __forceinline__ float funmap(uint32_t m) {
    uint32_t u = (m & 0x80000000u) ? (m & 0x7fffffffu) : ~m;
    return __uint_as_float(u);
}

static __device__ __forceinline__ void warp_amax(float& v, int& i) {
#pragma unroll
    for (int o = 16; o; o >>= 1) {
        float v2 = __shfl_down_sync(0xffffffffu, v, o);
        int   i2 = __shfl_down_sync(0xffffffffu, i, o);
        if (v2 > v || (v2 == v && i2 < i)) { v = v2; i = i2; }
    }
}

// ---------------------------------------------------------------------------
// One CTA per batch row b.
// Phase A: logits -> per-split softmax -> logp in SMEM; best = argmax p.
// Phase B: 10 gumbel-argmaxes with conservative integer screening:
//   exact-logf gumbel evaluated ONLY when (bits>>9) beats a warp-synced
//   threshold derived from the warp-wide running max (provably lenient).
// ---------------------------------------------------------------------------
__global__ void __launch_bounds__(TPB) rd_kernel(
    const float* __restrict__ X,     // (8192, 12288)
    const float* __restrict__ W,     // (3, 3)
    const float* __restrict__ Bvec,  // (3,)
    float* __restrict__ out)         // (8192,) float32
{
    __shared__ float sh[H_ALL];            // logits -> exp -> logp
    __shared__ float s_red[3][8];
    __shared__ float s_max[3];
    __shared__ float s_sum[3];
    __shared__ float s_wv[N_E + 1][8];
    __shared__ int   s_wi[N_E + 1][8];
    __shared__ int   s_res[N_E + 1];

    const int b    = blockIdx.x;
    const int tid  = threadIdx.x;
    const int wid  = tid >> 5;
    const int lane = tid & 31;

    const float* xr = X + (size_t)b * (H_ALL * 3);

    const float w00 = W[0], w01 = W[1], w02 = W[2];
    const float w10 = W[3], w11 = W[4], w12 = W[5];
    const float w20 = W[6], w21 = W[7], w22 = W[8];
    const float bb0 = Bvec[0], bb1 = Bvec[1], bb2 = Bvec[2];

    // ---- logits + per-split max (splits: [0,2048), [2048,3072), [3072,4096))
    float lm0 = NEG_BIG, lm1 = NEG_BIG, lm2 = NEG_BIG;
#pragma unroll
    for (int j = 0; j < 16; j++) {
        const int h = tid + j * TPB;
        const float x0 = xr[3 * h + 0], x1 = xr[3 * h + 1], x2 = xr[3 * h + 2];
        float l;
        if (j < 8)       l = fmaf(x2, w02, fmaf(x1, w01, x0 * w00)) + bb0;
        else if (j < 12) l = fmaf(x2, w12, fmaf(x1, w11, x0 * w10)) + bb1;
        else             l = fmaf(x2, w22, fmaf(x1, w21, x0 * w20)) + bb2;
        sh[h] = l;
        if (j < 8)       lm0 = fmaxf(lm0, l);
        else if (j < 12) lm1 = fmaxf(lm1, l);
        else             lm2 = fmaxf(lm2, l);
    }
#pragma unroll
    for (int o = 16; o; o >>= 1) {
        lm0 = fmaxf(lm0, __shfl_xor_sync(0xffffffffu, lm0, o));
        lm1 = fmaxf(lm1, __shfl_xor_sync(0xffffffffu, lm1, o));
        lm2 = fmaxf(lm2, __shfl_xor_sync(0xffffffffu, lm2, o));
    }
    if (!lane) { s_red[0][wid] = lm0; s_red[1][wid] = lm1; s_red[2][wid] = lm2; }
    __syncthreads();
    if (tid < 3) {
        float m = s_red[tid][0];
#pragma unroll
        for (int k = 1; k < 8; k++) m = fmaxf(m, s_red[tid][k]);
        s_max[tid] = m;
    }
    __syncthreads();

    // ---- exp(l - max) and per-split sums
    const float m0 = s_max[0], m1 = s_max[1], m2 = s_max[2];
    float ls0 = 0.f, ls1 = 0.f, ls2 = 0.f;
#pragma unroll
    for (int j = 0; j < 16; j++) {
        const int h = tid + j * TPB;
        const float m = (j < 8) ? m0 : ((j < 12) ? m1 : m2);
        const float e = expf(sh[h] - m);
        sh[h] = e;
        if (j < 8) ls0 += e; else if (j < 12) ls1 += e; else ls2 += e;
    }
#pragma unroll
    for (int o = 16; o; o >>= 1) {
        ls0 += __shfl_xor_sync(0xffffffffu, ls0, o);
        ls1 += __shfl_xor_sync(0xffffffffu, ls1, o);
        ls2 += __shfl_xor_sync(0xffffffffu, ls2, o);
    }
    if (!lane) { s_red[0][wid] = ls0; s_red[1][wid] = ls1; s_red[2][wid] = ls2; }
    __syncthreads();
    if (tid < 3) {
        float s = s_red[tid][0];
#pragma unroll
        for (int k = 1; k < 8; k++) s += s_red[tid][k];
        s_sum[tid] = s;
    }
    __syncthreads();

    // ---- p = e/s (best = argmax of concatenated probs), logp into SMEM
    const float su0 = s_sum[0], su1 = s_sum[1], su2 = s_sum[2];
    float bv = -1.0f; int bi = 0x7fffffff;
#pragma unroll
    for (int j = 0; j < 16; j++) {
        const int h = tid + j * TPB;
        const float s = (j < 8) ? su0 : ((j < 12) ? su1 : su2);
        const float p = sh[h] / s;
        if (p > bv) { bv = p; bi = h; }
        sh[h] = logf(p);
    }

    // Upper bound on every logp (e <= 1 so p <= 1/su); +1e-5 covers div/log ULPs.
    const float lpmax =
        fmaxf(fmaxf(-logf(su0), -logf(su1)), -logf(su2)) + 1e-5f;

    // ---- Phase B: 10 screened gumbel-argmax draws; count = e*2^25 + b*4096 + h
    float    mv[N_E]; int mi[N_E];
    int      thr[N_E];            // integer screen threshold on (bits>>9)
    uint32_t tsrc[N_E];           // mapped warp-max the threshold was built from
#pragma unroll
    for (int e = 0; e < N_E; e++) { mv[e] = NEG_BIG; mi[e] = 0; thr[e] = -1; tsrc[e] = 0u; }

    const uint32_t cbase = ((uint32_t)b << 12);
#pragma unroll 1
    for (int j = 0; j < N_ITER; j++) {
        const int h = tid + j * TPB;
        const float lp = sh[h];
        const uint32_t c = cbase + (uint32_t)h;
#pragma unroll
        for (int e = 0; e < N_E; e++) {
            const int mbits =
                (int)(tf2x32_xor(c + (uint32_t)e * E_STRIDE) >> 9);
            if (mbits > thr[e]) {                       // conservative screen
                float f = __uint_as_float((uint32_t)mbits | 0x3f800000u) - 1.0f;
                if (f == 0.0f) f = 1.17549435e-38f;     // float32 tiny
                const float v = -logf(-logf(f)) + lp;   // exact gumbel path
                if (v > mv[e]) { mv[e] = v; mi[e] = h; }
            }
        }
        if (j < N_ITER - 1) {
            // warp-coordinated threshold refresh (screen is lenient by margin)
#pragma unroll
            for (int e = 0; e < N_E; e++) {
                const uint32_t wm = __reduce_max_sync(0xffffffffu, fmap(mv[e]));
                if (wm > tsrc[e]) {                     // warp-uniform branch
                    tsrc[e] = wm;
                    const float T  = funmap(wm) - lpmax;       // needed gumbel
                    const float ut = __expf(-__expf(-T));      // u threshold
                    // 2^23 * (1 - 1.5e-5) margin, minus 4: strictly lenient
                    thr[e] = (int)(ut * 8388480.0f) - 4;
                }
            }
        }
    }

    // ---- block argmax reductions: slot 0 = best(prob), slots 1..10 = draws
    warp_amax(bv, bi);
    if (!lane) { s_wv[0][wid] = bv; s_wi[0][wid] = bi; }
#pragma unroll
    for (int e = 0; e < N_E; e++) {
        float v = mv[e]; int i = mi[e];
        warp_amax(v, i);
        if (!lane) { s_wv[e + 1][wid] = v; s_wi[e + 1][wid] = i; }
    }
    __syncthreads();
    if (tid < N_E + 1) {
        float v = s_wv[tid][0]; int i = s_wi[tid][0];
#pragma unroll
        for (int k = 1; k < 8; k++) {
            const float v2 = s_wv[tid][k]; const int i2 = s_wi[tid][k];
            if (v2 > v || (v2 == v && i2 < i)) { v = v2; i = i2; }
        }
        s_res[tid] = i;
    }
    __syncthreads();
    if (tid == 0) {
        const int best = s_res[0];
        bool hit = false;
#pragma unroll
        for (int e = 1; e <= N_E; e++) hit = hit || (s_res[e] == best);
        out[b] = (float)(hit ? best : s_res[N_E]);   // samples[-1] is draw e=9
    }
}

extern "C" void kernel_launch(void* const* d_in, const int* in_sizes, int n_in,
                              void* d_out, int out_size) {
    (void)in_sizes; (void)n_in; (void)out_size;
    const float* X = (const float*)d_in[0];
    const float* W = (const float*)d_in[1];
    const float* b = (const float*)d_in[2];
    rd_kernel<<<B_TOT, TPB>>>(X, W, b, (float*)d_out);
}

// round 10
// speedup vs baseline: 1.0557x; 1.0557x over previous
#include <cuda_runtime.h>
#include <stdint.h>
#include <stddef.h>

// Problem constants (ReinforceDistributed): B=8192, HALL=4096, C=3, EPS=10
#define B_TOT    8192
#define H_ALL    4096
#define N_E      10
#define E_STRIDE 33554432u     // 8192 * 4096 = 2^25
#define TPB      256
#define N_ITER   (H_ALL / TPB) // 16
#define NEG_BIG  (-3.0e38f)

// Opaque 1: ptxas cannot prove the multiplicand is 1, so mad.lo.u32 survives
// as IMAD (fma pipe) instead of being strength-reduced to IADD3 (alu pipe).
__device__ uint32_t g_one = 1u;

// ---------------------------------------------------------------------------
// JAX threefry2x32, key (0, 42), partitionable path (confirmed R8/R9):
//   bits[i] = out0 ^ out1 of block (c0=0, c1=i)
// ks0 = 0, ks1 = 42, ks2 = 0x1BD11BDA ^ 0 ^ 42 = 0x1BD11BF0
// All adds are issued as IMAD (a*one + b) to offload the saturated alu pipe;
// arithmetic is mod-2^32 identical, so the stream stays bit-exact.
// ---------------------------------------------------------------------------
static __device__ __forceinline__ uint32_t rotl32(uint32_t x, uint32_t r) {
    return __funnelshift_l(x, x, r);
}

#define ADDF(d, a, b) \
    asm("mad.lo.u32 %0, %1, %2, %3;" : "=r"(d) : "r"(a), "r"(one), "r"(b))

static __device__ __forceinline__ uint32_t tf2x32_xor(uint32_t cnt, uint32_t one) {
    const uint32_t ks1 = 42u;
    const uint32_t ks2 = 0x1BD11BF0u;
    uint32_t x0 = 0u;          // counts_hi (0) + ks0 (0)
    uint32_t x1 = cnt + ks1;   // counts_lo + ks1 (pre-loop, 1 add)
#define TFR(r) { ADDF(x0, x0, x1); x1 = rotl32(x1, (r)); x1 ^= x0; }
    TFR(13) TFR(15) TFR(26) TFR(6)
    ADDF(x0, x0, ks1); ADDF(x1, x1, ks2 + 1u);
    TFR(17) TFR(29) TFR(16) TFR(24)
    ADDF(x0, x0, ks2); ADDF(x1, x1, 2u);            // + ks0(0) + 2
    TFR(13) TFR(15) TFR(26) TFR(6)
    /* x0 += ks0 (0) */ ADDF(x1, x1, ks1 + 3u);
    TFR(17) TFR(29) TFR(16) TFR(24)
    ADDF(x0, x0, ks1); ADDF(x1, x1, ks2 + 4u);
    TFR(13) TFR(15) TFR(26) TFR(6)
    ADDF(x0, x0, ks2); ADDF(x1, x1, 5u);            // + ks0(0) + 5
#undef TFR
    return x0 ^ x1;
}

// order-preserving float<->uint map (total order on IEEE floats)
static __device__ __forceinline__ uint32_t fmap(float f) {
    uint32_t u = __float_as_uint(f);
    return (u & 0x80000000u) ? ~u : (u | 0x80000000u);
}
static __device__ __forceinline__ float funmap(uint32_t m) {
    uint32_t u = (m & 0x80000000u) ? (m & 0x7fffffffu) : ~m;
    return __uint_as_float(u);
}

static __device__ __forceinline__ void warp_amax(float& v, int& i) {
#pragma unroll
    for (int o = 16; o; o >>= 1) {
        float v2 = __shfl_down_sync(0xffffffffu, v, o);
        int   i2 = __shfl_down_sync(0xffffffffu, i, o);
        if (v2 > v || (v2 == v && i2 < i)) { v = v2; i = i2; }
    }
}

// ---------------------------------------------------------------------------
// One CTA per batch row b.
// Phase A: logits -> per-split softmax -> logp in SMEM; best = argmax p.
// Phase B: 10 gumbel-argmaxes with conservative integer screening (provably
//   lenient: exact-logf gumbel only when (bits>>9) beats warp-synced threshold).
// ---------------------------------------------------------------------------
__global__ void __launch_bounds__(TPB) rd_kernel(
    const float* __restrict__ X,     // (8192, 12288)
    const float* __restrict__ W,     // (3, 3)
    const float* __restrict__ Bvec,  // (3,)
    float* __restrict__ out)         // (8192,) float32
{
    __shared__ float sh[H_ALL];            // logits -> exp -> logp
    __shared__ float s_red[3][8];
    __shared__ float s_max[3];
    __shared__ float s_sum[3];
    __shared__ float s_wv[N_E + 1][8];
    __shared__ int   s_wi[N_E + 1][8];
    __shared__ int   s_res[N_E + 1];

    const int b    = blockIdx.x;
    const int tid  = threadIdx.x;
    const int wid  = tid >> 5;
    const int lane = tid & 31;

    const uint32_t one = *(volatile uint32_t*)&g_one;   // opaque 1 for IMAD adds

    const float* xr = X + (size_t)b * (H_ALL * 3);

    const float w00 = W[0], w01 = W[1], w02 = W[2];
    const float w10 = W[3], w11 = W[4], w12 = W[5];
    const float w20 = W[6], w21 = W[7], w22 = W[8];
    const float bb0 = Bvec[0], bb1 = Bvec[1], bb2 = Bvec[2];

    // ---- logits + per-split max (splits: [0,2048), [2048,3072), [3072,4096))
    float lm0 = NEG_BIG, lm1 = NEG_BIG, lm2 = NEG_BIG;
#pragma unroll
    for (int j = 0; j < 16; j++) {
        const int h = tid + j * TPB;
        const float x0 = xr[3 * h + 0], x1 = xr[3 * h + 1], x2 = xr[3 * h + 2];
        float l;
        if (j < 8)       l = fmaf(x2, w02, fmaf(x1, w01, x0 * w00)) + bb0;
        else if (j < 12) l = fmaf(x2, w12, fmaf(x1, w11, x0 * w10)) + bb1;
        else             l = fmaf(x2, w22, fmaf(x1, w21, x0 * w20)) + bb2;
        sh[h] = l;
        if (j < 8)       lm0 = fmaxf(lm0, l);
        else if (j < 12) lm1 = fmaxf(lm1, l);
        else             lm2 = fmaxf(lm2, l);
    }
#pragma unroll
    for (int o = 16; o; o >>= 1) {
        lm0 = fmaxf(lm0, __shfl_xor_sync(0xffffffffu, lm0, o));
        lm1 = fmaxf(lm1, __shfl_xor_sync(0xffffffffu, lm1, o));
        lm2 = fmaxf(lm2, __shfl_xor_sync(0xffffffffu, lm2, o));
    }
    if (!lane) { s_red[0][wid] = lm0; s_red[1][wid] = lm1; s_red[2][wid] = lm2; }
    __syncthreads();
    if (tid < 3) {
        float m = s_red[tid][0];
#pragma unroll
        for (int k = 1; k < 8; k++) m = fmaxf(m, s_red[tid][k]);
        s_max[tid] = m;
    }
    __syncthreads();

    // ---- exp(l - max) and per-split sums
    const float m0 = s_max[0], m1 = s_max[1], m2 = s_max[2];
    float ls0 = 0.f, ls1 = 0.f, ls2 = 0.f;
#pragma unroll
    for (int j = 0; j < 16; j++) {
        const int h = tid + j * TPB;
        const float m = (j < 8) ? m0 : ((j < 12) ? m1 : m2);
        const float e = expf(sh[h] - m);
        sh[h] = e;
        if (j < 8) ls0 += e; else if (j < 12) ls1 += e; else ls2 += e;
    }
#pragma unroll
    for (int o = 16; o; o >>= 1) {
        ls0 += __shfl_xor_sync(0xffffffffu, ls0, o);
        ls1 += __shfl_xor_sync(0xffffffffu, ls1, o);
        ls2 += __shfl_xor_sync(0xffffffffu, ls2, o);
    }
    if (!lane) { s_red[0][wid] = ls0; s_red[1][wid] = ls1; s_red[2][wid] = ls2; }
    __syncthreads();
    if (tid < 3) {
        float s = s_red[tid][0];
#pragma unroll
        for (int k = 1; k < 8; k++) s += s_red[tid][k];
        s_sum[tid] = s;
    }
    __syncthreads();

    // ---- p = e/s (best = argmax of concatenated probs), logp into SMEM
    const float su0 = s_sum[0], su1 = s_sum[1], su2 = s_sum[2];
    float bv = -1.0f; int bi = 0x7fffffff;
#pragma unroll
    for (int j = 0; j < 16; j++) {
        const int h = tid + j * TPB;
        const float s = (j < 8) ? su0 : ((j < 12) ? su1 : su2);
        const float p = sh[h] / s;
        if (p > bv) { bv = p; bi = h; }
        sh[h] = logf(p);
    }

    // Upper bound on every logp (e <= 1 so p <= 1/su); +1e-5 covers div/log ULPs.
    const float lpmax =
        fmaxf(fmaxf(-logf(su0), -logf(su1)), -logf(su2)) + 1e-5f;

    // ---- Phase B: 10 screened gumbel-argmax draws; count = e*2^25 + b*4096 + h
    float    mv[N_E]; int mi[N_E];
    int      thr[N_E];            // integer screen threshold on (bits>>9)
    uint32_t tsrc[N_E];           // mapped warp-max the threshold was built from
#pragma unroll
    for (int e = 0; e < N_E; e++) { mv[e] = NEG_BIG; mi[e] = 0; thr[e] = -1; tsrc[e] = 0u; }

    const uint32_t cbase = ((uint32_t)b << 12);
#pragma unroll 1
    for (int j = 0; j < N_ITER; j++) {
        const int h = tid + j * TPB;
        const float lp = sh[h];
        const uint32_t c = cbase + (uint32_t)h;
#pragma unroll
        for (int e = 0; e < N_E; e++) {
            const int mbits =
                (int)(tf2x32_xor(c + (uint32_t)e * E_STRIDE, one) >> 9);
            if (mbits > thr[e]) {                       // conservative screen
                float f = __uint_as_float((uint32_t)mbits | 0x3f800000u) - 1.0f;
                if (f == 0.0f) f = 1.17549435e-38f;     // float32 tiny
                const float v = -logf(-logf(f)) + lp;   // exact gumbel path
                if (v > mv[e]) { mv[e] = v; mi[e] = h; }
            }
        }
        if (j < N_ITER - 1) {
            // warp-coordinated threshold refresh (screen is lenient by margin)
#pragma unroll
            for (int e = 0; e < N_E; e++) {
                const uint32_t wm = __reduce_max_sync(0xffffffffu, fmap(mv[e]));
                if (wm > tsrc[e]) {                     // warp-uniform branch
                    tsrc[e] = wm;
                    const float T  = funmap(wm) - lpmax;       // needed gumbel
                    const float ut = __expf(-__expf(-T));      // u threshold
                    // 2^23 * (1 - 1.5e-5) margin, minus 4: strictly lenient
                    thr[e] = (int)(ut * 8388480.0f) - 4;
                }
            }
        }
    }

    // ---- block argmax reductions: slot 0 = best(prob), slots 1..10 = draws
    warp_amax(bv, bi);
    if (!lane) { s_wv[0][wid] = bv; s_wi[0][wid] = bi; }
#pragma unroll
    for (int e = 0; e < N_E; e++) {
        float v = mv[e]; int i = mi[e];
        warp_amax(v, i);
        if (!lane) { s_wv[e + 1][wid] = v; s_wi[e + 1][wid] = i; }
    }
    __syncthreads();
    if (tid < N_E + 1) {
        float v = s_wv[tid][0]; int i = s_wi[tid][0];
#pragma unroll
        for (int k = 1; k < 8; k++) {
            const float v2 = s_wv[tid][k]; const int i2 = s_wi[tid][k];
            if (v2 > v || (v2 == v && i2 < i)) { v = v2; i = i2; }
        }
        s_res[tid] = i;
    }
    __syncthreads();
    if (tid == 0) {
        const int best = s_res[0];
        bool hit = false;
#pragma unroll
        for (int e = 1; e <= N_E; e++) hit = hit || (s_res[e] == best);
        out[b] = (float)(hit ? best : s_res[N_E]);   // samples[-1] is draw e=9
    }
}

extern "C" void kernel_launch(void* const* d_in, const int* in_sizes, int n_in,
                              void* d_out, int out_size) {
    (void)in_sizes; (void)n_in; (void)out_size;
    const float* X = (const float*)d_in[0];
    const float* W = (const float*)d_in[1];
    const float* b = (const float*)d_in[2];
    rd_kernel<<<B_TOT, TPB>>>(X, W, b, (float*)d_out);
}

// round 11
// speedup vs baseline: 4.1228x; 3.9053x over previous
#include <cuda_runtime.h>
#include <stdint.h>
#include <stddef.h>

// Problem constants (ReinforceDistributed): B=8192, HALL=4096, C=3, EPS=10
#define B_TOT    8192
#define H_ALL    4096
#define N_E      10
#define E_STRIDE 33554432u     // 8192 * 4096 = 2^25
#define TPB      256
#define N_ITER   (H_ALL / TPB) // 16
#define NEG_BIG  (-3.0e38f)

// Opaque 1: keeps mad.lo.u32 as IMAD (fma pipe) instead of IADD3 (alu pipe).
__device__ uint32_t g_one = 1u;

// ---------------------------------------------------------------------------
// JAX threefry2x32, key (0, 42), partitionable path (confirmed R8/R9):
//   bits[i] = out0 ^ out1 of block (c0=0, c1=i)
// ks0 = 0, ks1 = 42, ks2 = 0x1BD11BDA ^ 0 ^ 42 = 0x1BD11BF0
// Adds issued as IMAD (a*one + b): fma-pipe offload, mod-2^32 identical.
// ---------------------------------------------------------------------------
static __device__ __forceinline__ uint32_t rotl32(uint32_t x, uint32_t r) {
    return __funnelshift_l(x, x, r);
}

#define ADDF(d, a, b) \
    asm("mad.lo.u32 %0, %1, %2, %3;" : "=r"(d) : "r"(a), "r"(one), "r"(b))

static __device__ __forceinline__ uint32_t tf2x32_xor(uint32_t cnt, uint32_t one) {
    const uint32_t ks1 = 42u;
    const uint32_t ks2 = 0x1BD11BF0u;
    uint32_t x0 = 0u;          // counts_hi (0) + ks0 (0)
    uint32_t x1 = cnt + ks1;   // counts_lo + ks1
#define TFR(r) { ADDF(x0, x0, x1); x1 = rotl32(x1, (r)); x1 ^= x0; }
    TFR(13) TFR(15) TFR(26) TFR(6)
    ADDF(x0, x0, ks1); ADDF(x1, x1, ks2 + 1u);
    TFR(17) TFR(29) TFR(16) TFR(24)
    ADDF(x0, x0, ks2); ADDF(x1, x1, 2u);            // + ks0(0) + 2
    TFR(13) TFR(15) TFR(26) TFR(6)
    /* x0 += ks0 (0) */ ADDF(x1, x1, ks1 + 3u);
    TFR(17) TFR(29) TFR(16) TFR(24)
    ADDF(x0, x0, ks1); ADDF(x1, x1, ks2 + 4u);
    TFR(13) TFR(15) TFR(26) TFR(6)
    ADDF(x0, x0, ks2); ADDF(x1, x1, 5u);            // + ks0(0) + 5
#undef TFR
    return x0 ^ x1;
}

// exact gumbel from mantissa bits (bits>>9), matching JAX bit-for-bit
static __device__ __forceinline__ float gumbel_mbits(uint32_t mbits) {
    float f = __uint_as_float(mbits | 0x3f800000u) - 1.0f;
    if (f == 0.0f) f = 1.17549435e-38f;   // float32 tiny
    return -logf(-logf(f));
}

// order-preserving float<->uint map (total order on IEEE floats)
static __device__ __forceinline__ uint32_t fmap(float f) {
    uint32_t u = __float_as_uint(f);
    return (u & 0x80000000u) ? ~u : (u | 0x80000000u);
}
static __device__ __forceinline__ float funmap(uint32_t m) {
    uint32_t u = (m & 0x80000000u) ? (m & 0x7fffffffu) : ~m;
    return __uint_as_float(u);
}

// lenient integer screen threshold on (bits>>9) for "gumbel could reach T-lpmax"
static __device__ __forceinline__ int screen_thr(float T, float lpmax) {
    const float ut = __expf(-__expf(-(T - lpmax)));
    return (int)(ut * 8388480.0f) - 4;   // 2^23*(1-1.5e-5) margin, -4: lenient
}

static __device__ __forceinline__ void warp_amax(float& v, int& i) {
#pragma unroll
    for (int o = 16; o; o >>= 1) {
        float v2 = __shfl_down_sync(0xffffffffu, v, o);
        int   i2 = __shfl_down_sync(0xffffffffu, i, o);
        if (v2 > v || (v2 == v && i2 < i)) { v = v2; i = i2; }
    }
}

// ---------------------------------------------------------------------------
// One CTA per batch row b.
// Phase A: logits -> per-split softmax -> logp in SMEM; best = argmax p.
// Phase B: draws 0..8 -> early-kill hit test vs best's own gumbel score T_e
//          (first exact-verified exceeder kills the draw CTA-wide);
//          draw 9 -> full screened gumbel-argmax (needed as samples[-1]).
// All exact comparisons use the identical fp path as the reference scan.
// ---------------------------------------------------------------------------
__global__ void __launch_bounds__(TPB) rd_kernel(
    const float* __restrict__ X,     // (8192, 12288)
    const float* __restrict__ W,     // (3, 3)
    const float* __restrict__ Bvec,  // (3,)
    float* __restrict__ out)         // (8192,) float32
{
    __shared__ float sh[H_ALL];            // logits -> exp -> logp
    __shared__ float s_red[3][8];
    __shared__ float s_max[3];
    __shared__ float s_sum[3];
    __shared__ float s_bv[8];
    __shared__ int   s_bi[8];
    __shared__ int   s_best;
    volatile __shared__ int s_alive[9];    // draws 0..8: argmax==best still possible
    __shared__ float s_T[9];               // exact best-score per draw
    __shared__ int   s_thr[9];             // fixed lenient integer screens
    __shared__ float s_w9v[8];
    __shared__ int   s_w9i[8];

    const int b    = blockIdx.x;
    const int tid  = threadIdx.x;
    const int wid  = tid >> 5;
    const int lane = tid & 31;

    const uint32_t one = *(volatile uint32_t*)&g_one;   // opaque 1 for IMAD adds

    const float* xr = X + (size_t)b * (H_ALL * 3);

    const float w00 = W[0], w01 = W[1], w02 = W[2];
    const float w10 = W[3], w11 = W[4], w12 = W[5];
    const float w20 = W[6], w21 = W[7], w22 = W[8];
    const float bb0 = Bvec[0], bb1 = Bvec[1], bb2 = Bvec[2];

    // ---- logits + per-split max (splits: [0,2048), [2048,3072), [3072,4096))
    float lm0 = NEG_BIG, lm1 = NEG_BIG, lm2 = NEG_BIG;
#pragma unroll
    for (int j = 0; j < 16; j++) {
        const int h = tid + j * TPB;
        const float x0 = xr[3 * h + 0], x1 = xr[3 * h + 1], x2 = xr[3 * h + 2];
        float l;
        if (j < 8)       l = fmaf(x2, w02, fmaf(x1, w01, x0 * w00)) + bb0;
        else if (j < 12) l = fmaf(x2, w12, fmaf(x1, w11, x0 * w10)) + bb1;
        else             l = fmaf(x2, w22, fmaf(x1, w21, x0 * w20)) + bb2;
        sh[h] = l;
        if (j < 8)       lm0 = fmaxf(lm0, l);
        else if (j < 12) lm1 = fmaxf(lm1, l);
        else             lm2 = fmaxf(lm2, l);
    }
#pragma unroll
    for (int o = 16; o; o >>= 1) {
        lm0 = fmaxf(lm0, __shfl_xor_sync(0xffffffffu, lm0, o));
        lm1 = fmaxf(lm1, __shfl_xor_sync(0xffffffffu, lm1, o));
        lm2 = fmaxf(lm2, __shfl_xor_sync(0xffffffffu, lm2, o));
    }
    if (!lane) { s_red[0][wid] = lm0; s_red[1][wid] = lm1; s_red[2][wid] = lm2; }
    __syncthreads();
    if (tid < 3) {
        float m = s_red[tid][0];
#pragma unroll
        for (int k = 1; k < 8; k++) m = fmaxf(m, s_red[tid][k]);
        s_max[tid] = m;
    }
    __syncthreads();

    // ---- exp(l - max) and per-split sums
    const float m0 = s_max[0], m1 = s_max[1], m2 = s_max[2];
    float ls0 = 0.f, ls1 = 0.f, ls2 = 0.f;
#pragma unroll
    for (int j = 0; j < 16; j++) {
        const int h = tid + j * TPB;
        const float m = (j < 8) ? m0 : ((j < 12) ? m1 : m2);
        const float e = expf(sh[h] - m);
        sh[h] = e;
        if (j < 8) ls0 += e; else if (j < 12) ls1 += e; else ls2 += e;
    }
#pragma unroll
    for (int o = 16; o; o >>= 1) {
        ls0 += __shfl_xor_sync(0xffffffffu, ls0, o);
        ls1 += __shfl_xor_sync(0xffffffffu, ls1, o);
        ls2 += __shfl_xor_sync(0xffffffffu, ls2, o);
    }
    if (!lane) { s_red[0][wid] = ls0; s_red[1][wid] = ls1; s_red[2][wid] = ls2; }
    __syncthreads();
    if (tid < 3) {
        float s = s_red[tid][0];
#pragma unroll
        for (int k = 1; k < 8; k++) s += s_red[tid][k];
        s_sum[tid] = s;
    }
    __syncthreads();

    // ---- p = e/s (best = argmax of concatenated probs), logp into SMEM
    const float su0 = s_sum[0], su1 = s_sum[1], su2 = s_sum[2];
    float bv = -1.0f; int bi = 0x7fffffff;
#pragma unroll
    for (int j = 0; j < 16; j++) {
        const int h = tid + j * TPB;
        const float s = (j < 8) ? su0 : ((j < 12) ? su1 : su2);
        const float p = sh[h] / s;
        if (p > bv) { bv = p; bi = h; }
        sh[h] = logf(p);
    }

    // Upper bound on every logp (e <= 1 so p <= 1/su); +1e-5 covers div/log ULPs.
    const float lpmax =
        fmaxf(fmaxf(-logf(su0), -logf(su1)), -logf(su2)) + 1e-5f;

    // ---- block-reduce best BEFORE Phase B (needed for T_e)
    warp_amax(bv, bi);
    if (!lane) { s_bv[wid] = bv; s_bi[wid] = bi; }
    if (tid < 9) s_alive[tid] = 1;
    __syncthreads();
    if (tid == 0) {
        float v = s_bv[0]; int i = s_bi[0];
#pragma unroll
        for (int k = 1; k < 8; k++) {
            if (s_bv[k] > v || (s_bv[k] == v && s_bi[k] < i)) { v = s_bv[k]; i = s_bi[k]; }
        }
        s_best = i;
    }
    __syncthreads();
    const int   best    = s_best;
    const float lp_best = sh[best];
    const uint32_t cbase = ((uint32_t)b << 12);

    // ---- T_e = exact gumbel score of `best` in draw e, + fixed screen thr
    if (tid < 9) {
        const uint32_t mb =
            tf2x32_xor(cbase + (uint32_t)best + (uint32_t)tid * E_STRIDE, one) >> 9;
        const float T = gumbel_mbits(mb) + lp_best;   // identical fp path
        s_T[tid]   = T;
        s_thr[tid] = screen_thr(T, lpmax);
    }
    __syncthreads();

    // ---- Phase B: early-kill scan (draws 0..8) + screened argmax (draw 9)
    float mv9 = NEG_BIG; int mi9 = 0;
    int thr9 = -1; uint32_t tsrc9 = 0u;

#pragma unroll 1
    for (int j = 0; j < N_ITER; j++) {
        const int h = tid + j * TPB;
        const float lp = sh[h];
        const uint32_t c = cbase + (uint32_t)h;

        // draws 0..8: kill if any h beats best's draw (first-index tie-break)
#pragma unroll
        for (int e = 0; e < 9; e++) {
            if (s_alive[e]) {
                const int mbits =
                    (int)(tf2x32_xor(c + (uint32_t)e * E_STRIDE, one) >> 9);
                if (mbits > s_thr[e]) {
                    const float v = gumbel_mbits((uint32_t)mbits) + lp;
                    const float T = s_T[e];
                    if (v > T || (v == T && h < best)) s_alive[e] = 0;
                }
            }
        }

        // draw 9: full screened running argmax (samples[-1])
        {
            const int mbits =
                (int)(tf2x32_xor(c + 9u * E_STRIDE, one) >> 9);
            if (mbits > thr9) {
                const float v = gumbel_mbits((uint32_t)mbits) + lp;
                if (v > mv9) { mv9 = v; mi9 = h; }
            }
            if (j < N_ITER - 1) {
                const uint32_t wm = __reduce_max_sync(0xffffffffu, fmap(mv9));
                if (wm > tsrc9) {               // warp-uniform branch
                    tsrc9 = wm;
                    thr9  = screen_thr(funmap(wm), lpmax);
                }
            }
        }
    }

    // ---- block argmax for draw 9, then output
    warp_amax(mv9, mi9);
    if (!lane) { s_w9v[wid] = mv9; s_w9i[wid] = mi9; }
    __syncthreads();
    if (tid == 0) {
        float v = s_w9v[0]; int a9 = s_w9i[0];
#pragma unroll
        for (int k = 1; k < 8; k++) {
            if (s_w9v[k] > v || (s_w9v[k] == v && s_w9i[k] < a9)) { v = s_w9v[k]; a9 = s_w9i[k]; }
        }
        bool hit = (a9 == best);
#pragma unroll
        for (int e = 0; e < 9; e++) hit = hit || (s_alive[e] != 0);
        out[b] = (float)(hit ? best : a9);
    }
}

extern "C" void kernel_launch(void* const* d_in, const int* in_sizes, int n_in,
                              void* d_out, int out_size) {
    (void)in_sizes; (void)n_in; (void)out_size;
    const float* X = (const float*)d_in[0];
    const float* W = (const float*)d_in[1];
    const float* b = (const float*)d_in[2];
    rd_kernel<<<B_TOT, TPB>>>(X, W, b, (float*)d_out);
}

// round 12
// speedup vs baseline: 5.5262x; 1.3404x over previous
#include <cuda_runtime.h>
#include <stdint.h>
#include <stddef.h>

// Problem constants (ReinforceDistributed): B=8192, HALL=4096, C=3, EPS=10
#define B_TOT    8192
#define H_ALL    4096
#define N_E      10
#define E_STRIDE 33554432u     // 8192 * 4096 = 2^25
#define TPB      256
#define N_ITER   (H_ALL / TPB) // 16
#define NEG_BIG  (-3.0e38f)

// Opaque 1: keeps mad.lo.u32 as IMAD (fma pipe) instead of IADD3 (alu pipe).
__device__ uint32_t g_one = 1u;

// ---------------------------------------------------------------------------
// JAX threefry2x32, key (0, 42), partitionable path (confirmed R8..R11):
//   bits[i] = out0 ^ out1 of block (c0=0, c1=i)
// ks0 = 0, ks1 = 42, ks2 = 0x1BD11BDA ^ 0 ^ 42 = 0x1BD11BF0
// Adds issued as IMAD (a*one + b): fma-pipe offload, mod-2^32 identical.
// Round 1 folded: x0 starts at 0 so its first add is a plain move.
// ---------------------------------------------------------------------------
static __device__ __forceinline__ uint32_t rotl32(uint32_t x, uint32_t r) {
    return __funnelshift_l(x, x, r);
}

#define ADDF(d, a, b) \
    asm("mad.lo.u32 %0, %1, %2, %3;" : "=r"(d) : "r"(a), "r"(one), "r"(b))

static __device__ __forceinline__ uint32_t tf2x32_xor(uint32_t cnt, uint32_t one) {
    const uint32_t ks1 = 42u;
    const uint32_t ks2 = 0x1BD11BF0u;
    uint32_t x1 = cnt + ks1;   // counts_lo + ks1
    uint32_t x0 = x1;          // round-1 add folded (0 + x1)
    x1 = rotl32(x1, 13); x1 ^= x0;
#define TFR(r) { ADDF(x0, x0, x1); x1 = rotl32(x1, (r)); x1 ^= x0; }
    TFR(15) TFR(26) TFR(6)
    ADDF(x0, x0, ks1); ADDF(x1, x1, ks2 + 1u);
    TFR(17) TFR(29) TFR(16) TFR(24)
    ADDF(x0, x0, ks2); ADDF(x1, x1, 2u);            // + ks0(0) + 2
    TFR(13) TFR(15) TFR(26) TFR(6)
    /* x0 += ks0 (0) */ ADDF(x1, x1, ks1 + 3u);
    TFR(17) TFR(29) TFR(16) TFR(24)
    ADDF(x0, x0, ks1); ADDF(x1, x1, ks2 + 4u);
    TFR(13) TFR(15) TFR(26) TFR(6)
    ADDF(x0, x0, ks2); ADDF(x1, x1, 5u);            // + ks0(0) + 5
#undef TFR
    return x0 ^ x1;
}

// exact gumbel from mantissa bits (bits>>9), matching JAX bit-for-bit
static __device__ __forceinline__ float gumbel_mbits(uint32_t mbits) {
    float f = __uint_as_float(mbits | 0x3f800000u) - 1.0f;
    if (f == 0.0f) f = 1.17549435e-38f;   // float32 tiny
    return -logf(-logf(f));
}

// order-preserving float<->uint map (total order on IEEE floats)
static __device__ __forceinline__ uint32_t fmap(float f) {
    uint32_t u = __float_as_uint(f);
    return (u & 0x80000000u) ? ~u : (u | 0x80000000u);
}
static __device__ __forceinline__ float funmap(uint32_t m) {
    uint32_t u = (m & 0x80000000u) ? (m & 0x7fffffffu) : ~m;
    return __uint_as_float(u);
}

// lenient integer screen threshold on (bits>>9) for "gumbel could reach T-lpmax"
static __device__ __forceinline__ int screen_thr(float T, float lpmax) {
    const float ut = __expf(-__expf(-(T - lpmax)));
    return (int)(ut * 8388480.0f) - 4;   // 2^23*(1-1.5e-5) margin, -4: lenient
}

static __device__ __forceinline__ void warp_amax(float& v, int& i) {
#pragma unroll
    for (int o = 16; o; o >>= 1) {
        float v2 = __shfl_down_sync(0xffffffffu, v, o);
        int   i2 = __shfl_down_sync(0xffffffffu, i, o);
        if (v2 > v || (v2 == v && i2 < i)) { v = v2; i = i2; }
    }
}

// ---------------------------------------------------------------------------
// One CTA per batch row b.
// Phase A: logits -> per-split softmax -> p in SMEM; best = argmax p.
//          (logf(p) deferred to screen-pass sites: identical float result)
// Phase B: draws 0..8 -> warp-specialized early-kill scans (warp w owns draw
//          w, warp 0 also draw 8; 32-h chunks, ballot break; ~1 chunk typ.);
//          draw 9 -> full screened gumbel-argmax over all h (samples[-1]).
// ---------------------------------------------------------------------------
__global__ void __launch_bounds__(TPB) rd_kernel(
    const float* __restrict__ X,     // (8192, 12288)
    const float* __restrict__ W,     // (3, 3)
    const float* __restrict__ Bvec,  // (3,)
    float* __restrict__ out)         // (8192,) float32
{
    __shared__ float sh[H_ALL];            // logits -> exp -> p (softmax probs)
    __shared__ float s_red[3][8];
    __shared__ float s_max[3];
    __shared__ float s_sum[3];
    __shared__ float s_bv[8];
    __shared__ int   s_bi[8];
    __shared__ int   s_best;
    __shared__ int   s_alive[9];           // draws 0..8: hit still possible
    __shared__ float s_T[9];               // exact best-score per draw
    __shared__ int   s_thr[9];             // fixed lenient integer screens
    __shared__ float s_w9v[8];
    __shared__ int   s_w9i[8];

    const int b    = blockIdx.x;
    const int tid  = threadIdx.x;
    const int wid  = tid >> 5;
    const int lane = tid & 31;

    const uint32_t one = *(volatile uint32_t*)&g_one;   // opaque 1 for IMAD adds

    const float* xr = X + (size_t)b * (H_ALL * 3);

    const float w00 = W[0], w01 = W[1], w02 = W[2];
    const float w10 = W[3], w11 = W[4], w12 = W[5];
    const float w20 = W[6], w21 = W[7], w22 = W[8];
    const float bb0 = Bvec[0], bb1 = Bvec[1], bb2 = Bvec[2];

    // ---- logits + per-split max (splits: [0,2048), [2048,3072), [3072,4096))
    float lm0 = NEG_BIG, lm1 = NEG_BIG, lm2 = NEG_BIG;
#pragma unroll
    for (int j = 0; j < 16; j++) {
        const int h = tid + j * TPB;
        const float x0 = xr[3 * h + 0], x1 = xr[3 * h + 1], x2 = xr[3 * h + 2];
        float l;
        if (j < 8)       l = fmaf(x2, w02, fmaf(x1, w01, x0 * w00)) + bb0;
        else if (j < 12) l = fmaf(x2, w12, fmaf(x1, w11, x0 * w10)) + bb1;
        else             l = fmaf(x2, w22, fmaf(x1, w21, x0 * w20)) + bb2;
        sh[h] = l;
        if (j < 8)       lm0 = fmaxf(lm0, l);
        else if (j < 12) lm1 = fmaxf(lm1, l);
        else             lm2 = fmaxf(lm2, l);
    }
#pragma unroll
    for (int o = 16; o; o >>= 1) {
        lm0 = fmaxf(lm0, __shfl_xor_sync(0xffffffffu, lm0, o));
        lm1 = fmaxf(lm1, __shfl_xor_sync(0xffffffffu, lm1, o));
        lm2 = fmaxf(lm2, __shfl_xor_sync(0xffffffffu, lm2, o));
    }
    if (!lane) { s_red[0][wid] = lm0; s_red[1][wid] = lm1; s_red[2][wid] = lm2; }
    __syncthreads();
    if (tid < 3) {
        float m = s_red[tid][0];
#pragma unroll
        for (int k = 1; k < 8; k++) m = fmaxf(m, s_red[tid][k]);
        s_max[tid] = m;
    }
    __syncthreads();

    // ---- exp(l - max) and per-split sums
    const float m0 = s_max[0], m1 = s_max[1], m2 = s_max[2];
    float ls0 = 0.f, ls1 = 0.f, ls2 = 0.f;
#pragma unroll
    for (int j = 0; j < 16; j++) {
        const int h = tid + j * TPB;
        const float m = (j < 8) ? m0 : ((j < 12) ? m1 : m2);
        const float e = expf(sh[h] - m);
        sh[h] = e;
        if (j < 8) ls0 += e; else if (j < 12) ls1 += e; else ls2 += e;
    }
#pragma unroll
    for (int o = 16; o; o >>= 1) {
        ls0 += __shfl_xor_sync(0xffffffffu, ls0, o);
        ls1 += __shfl_xor_sync(0xffffffffu, ls1, o);
        ls2 += __shfl_xor_sync(0xffffffffu, ls2, o);
    }
    if (!lane) { s_red[0][wid] = ls0; s_red[1][wid] = ls1; s_red[2][wid] = ls2; }
    __syncthreads();
    if (tid < 3) {
        float s = s_red[tid][0];
#pragma unroll
        for (int k = 1; k < 8; k++) s += s_red[tid][k];
        s_sum[tid] = s;
    }
    __syncthreads();

    // ---- p = e/s into SMEM; best = argmax of concatenated probs
    const float su0 = s_sum[0], su1 = s_sum[1], su2 = s_sum[2];
    float bv = -1.0f; int bi = 0x7fffffff;
#pragma unroll
    for (int j = 0; j < 16; j++) {
        const int h = tid + j * TPB;
        const float s = (j < 8) ? su0 : ((j < 12) ? su1 : su2);
        const float p = sh[h] / s;
        if (p > bv) { bv = p; bi = h; }
        sh[h] = p;                         // logf(p) deferred to use sites
    }

    // Upper bound on every logp (e <= 1 so p <= 1/su); +1e-5 covers div/log ULPs.
    const float lpmax =
        fmaxf(fmaxf(-logf(su0), -logf(su1)), -logf(su2)) + 1e-5f;

    // ---- block-reduce best (needed for T_e)
    warp_amax(bv, bi);
    if (!lane) { s_bv[wid] = bv; s_bi[wid] = bi; }
    if (tid < 9) s_alive[tid] = 1;
    __syncthreads();
    if (tid == 0) {
        float v = s_bv[0]; int i = s_bi[0];
#pragma unroll
        for (int k = 1; k < 8; k++) {
            if (s_bv[k] > v || (s_bv[k] == v && s_bi[k] < i)) { v = s_bv[k]; i = s_bi[k]; }
        }
        s_best = i;
    }
    __syncthreads();
    const int   best    = s_best;
    const float lp_best = logf(sh[best]);
    const uint32_t cbase = ((uint32_t)b << 12);

    // ---- T_e = exact gumbel score of `best` in draw e, + fixed screen thr
    if (tid < 9) {
        const uint32_t mb =
            tf2x32_xor(cbase + (uint32_t)best + (uint32_t)tid * E_STRIDE, one) >> 9;
        const float T = gumbel_mbits(mb) + lp_best;   // identical fp path
        s_T[tid]   = T;
        s_thr[tid] = screen_thr(T, lpmax);
    }
    __syncthreads();

    // ---- warp-specialized early-kill scans for draws 0..8
    // warp w owns draw w; warp 0 also owns draw 8. 32-h chunks, ballot break.
    // Kill is existential (any h beating best's score) -> order-independent.
    for (int e = wid; e < 9; e += 8) {
        const float T  = s_T[e];
        const int   th = s_thr[e];
        const uint32_t ce = cbase + (uint32_t)e * E_STRIDE;
        bool killed = false;
#pragma unroll 1
        for (int k = 0; k < H_ALL / 32 && !killed; k++) {
            const int h = lane + k * 32;
            const int mbits = (int)(tf2x32_xor(ce + (uint32_t)h, one) >> 9);
            bool kill = false;
            if (mbits > th) {                               // lenient screen
                const float v = gumbel_mbits((uint32_t)mbits) + logf(sh[h]);
                kill = (v > T) || (v == T && h < best);     // exact verify
            }
            killed = (__ballot_sync(0xffffffffu, kill) != 0u);
        }
        if (killed && lane == 0) s_alive[e] = 0;
    }

    // ---- draw 9: full screened running argmax (samples[-1])
    float mv9 = NEG_BIG; int mi9 = 0;
    int thr9 = -1; uint32_t tsrc9 = 0u;
    const uint32_t c9 = cbase + 9u * E_STRIDE;
#pragma unroll 1
    for (int j = 0; j < N_ITER; j++) {
        const int h = tid + j * TPB;
        const int mbits = (int)(tf2x32_xor(c9 + (uint32_t)h, one) >> 9);
        if (mbits > thr9) {                                 // lenient screen
            const float v = gumbel_mbits((uint32_t)mbits) + logf(sh[h]);
            if (v > mv9) { mv9 = v; mi9 = h; }
        }
        if (j < N_ITER - 1) {
            const uint32_t wm = __reduce_max_sync(0xffffffffu, fmap(mv9));
            if (wm > tsrc9) {                               // warp-uniform
                tsrc9 = wm;
                thr9  = screen_thr(funmap(wm), lpmax);
            }
        }
    }

    // ---- block argmax for draw 9, then output
    warp_amax(mv9, mi9);
    if (!lane) { s_w9v[wid] = mv9; s_w9i[wid] = mi9; }
    __syncthreads();
    if (tid == 0) {
        float v = s_w9v[0]; int a9 = s_w9i[0];
#pragma unroll
        for (int k = 1; k < 8; k++) {
            if (s_w9v[k] > v || (s_w9v[k] == v && s_w9i[k] < a9)) { v = s_w9v[k]; a9 = s_w9i[k]; }
        }
        bool hit = (a9 == best);
#pragma unroll
        for (int e = 0; e < 9; e++) hit = hit || (s_alive[e] != 0);
        out[b] = (float)(hit ? best : a9);
    }
}

extern "C" void kernel_launch(void* const* d_in, const int* in_sizes, int n_in,
                              void* d_out, int out_size) {
    (void)in_sizes; (void)n_in; (void)out_size;
    const float* X = (const float*)d_in[0];
    const float* W = (const float*)d_in[1];
    const float* b = (const float*)d_in[2];
    rd_kernel<<<B_TOT, TPB>>>(X, W, b, (float*)d_out);
}

// round 13
// speedup vs baseline: 5.5593x; 1.0060x over previous
#include <cuda_runtime.h>
#include <stdint.h>
#include <stddef.h>

// Problem constants (ReinforceDistributed): B=8192, HALL=4096, C=3, EPS=10
#define B_TOT    8192
#define H_ALL    4096
#define N_E      10
#define E_STRIDE 33554432u     // 8192 * 4096 = 2^25
#define TPB      256
#define NEG_BIG  (-3.0e38f)

// Opaque 1: keeps mad.lo.u32 as IMAD (fma pipe) instead of IADD3 (alu pipe).
__device__ uint32_t g_one = 1u;

// ---------------------------------------------------------------------------
// JAX threefry2x32, key (0, 42), partitionable path (confirmed R8..R12):
//   bits[i] = out0 ^ out1 of block (c0=0, c1=i)
// ks0 = 0, ks1 = 42, ks2 = 0x1BD11BDA ^ 0 ^ 42 = 0x1BD11BF0
// Adds issued as IMAD (a*one + b): fma-pipe offload, mod-2^32 identical.
// Round 1 folded: x0 starts at 0 so its first add is a plain move.
// ---------------------------------------------------------------------------
static __device__ __forceinline__ uint32_t rotl32(uint32_t x, uint32_t r) {
    return __funnelshift_l(x, x, r);
}

#define ADDF(d, a, b) \
    asm("mad.lo.u32 %0, %1, %2, %3;" : "=r"(d) : "r"(a), "r"(one), "r"(b))

static __device__ __forceinline__ uint32_t tf2x32_xor(uint32_t cnt, uint32_t one) {
    const uint32_t ks1 = 42u;
    const uint32_t ks2 = 0x1BD11BF0u;
    uint32_t x1 = cnt + ks1;   // counts_lo + ks1
    uint32_t x0 = x1;          // round-1 add folded (0 + x1)
    x1 = rotl32(x1, 13); x1 ^= x0;
#define TFR(r) { ADDF(x0, x0, x1); x1 = rotl32(x1, (r)); x1 ^= x0; }
    TFR(15) TFR(26) TFR(6)
    ADDF(x0, x0, ks1); ADDF(x1, x1, ks2 + 1u);
    TFR(17) TFR(29) TFR(16) TFR(24)
    ADDF(x0, x0, ks2); ADDF(x1, x1, 2u);            // + ks0(0) + 2
    TFR(13) TFR(15) TFR(26) TFR(6)
    /* x0 += ks0 (0) */ ADDF(x1, x1, ks1 + 3u);
    TFR(17) TFR(29) TFR(16) TFR(24)
    ADDF(x0, x0, ks1); ADDF(x1, x1, ks2 + 4u);
    TFR(13) TFR(15) TFR(26) TFR(6)
    ADDF(x0, x0, ks2); ADDF(x1, x1, 5u);            // + ks0(0) + 5
#undef TFR
    return x0 ^ x1;
}

// exact gumbel from mantissa bits (bits>>9), matching JAX bit-for-bit
static __device__ __forceinline__ float gumbel_mbits(uint32_t mbits) {
    float f = __uint_as_float(mbits | 0x3f800000u) - 1.0f;
    if (f == 0.0f) f = 1.17549435e-38f;   // float32 tiny
    return -logf(-logf(f));
}

// order-preserving float<->uint map (total order on IEEE floats)
static __device__ __forceinline__ uint32_t fmap(float f) {
    uint32_t u = __float_as_uint(f);
    return (u & 0x80000000u) ? ~u : (u | 0x80000000u);
}
static __device__ __forceinline__ float funmap(uint32_t m) {
    uint32_t u = (m & 0x80000000u) ? (m & 0x7fffffffu) : ~m;
    return __uint_as_float(u);
}

// lenient raw-bits screen threshold: pass iff bits >= returned value.
// (bits>>9) > thr  <=>  bits >= (thr+1)<<9 ; thr=-1 -> 0 (always pass).
static __device__ __forceinline__ uint32_t screen_uthr(float T, float lpmax) {
    const float ut = __expf(-__expf(-(T - lpmax)));
    const int thr = (int)(ut * 8388480.0f) - 4;   // 2^23*(1-1.5e-5), -4: lenient
    return (uint32_t)(thr + 1) << 9;
}

static __device__ __forceinline__ void warp_amax(float& v, int& i) {
#pragma unroll
    for (int o = 16; o; o >>= 1) {
        float v2 = __shfl_down_sync(0xffffffffu, v, o);
        int   i2 = __shfl_down_sync(0xffffffffu, i, o);
        if (v2 > v || (v2 == v && i2 < i)) { v = v2; i = i2; }
    }
}

// ---------------------------------------------------------------------------
// One CTA per batch row b.
// Phase A: logits -> per-split softmax -> p in SMEM; best = argmax p; also
//          pmin (for a true lower bound lpmin used to seed draw-9's screen).
// Phase B: draws 0..8 -> warp-specialized early-kill scans (ballot break);
//          draw 9 -> screened gumbel-argmax, ILP2 (2 ciphers/iter), screen
//          seeded from warp-max raw bits + lpmin before any full eval.
// All exact comparisons use the identical fp path as the reference scan.
// ---------------------------------------------------------------------------
__global__ void __launch_bounds__(TPB) rd_kernel(
    const float* __restrict__ X,     // (8192, 12288)
    const float* __restrict__ W,     // (3, 3)
    const float* __restrict__ Bvec,  // (3,)
    float* __restrict__ out)         // (8192,) float32
{
    __shared__ float sh[H_ALL];            // logits -> exp -> p (softmax probs)
    __shared__ float s_red[3][8];
    __shared__ float s_max[3];
    __shared__ float s_sum[3];
    __shared__ float s_bv[8];
    __shared__ int   s_bi[8];
    __shared__ float s_pm[8];
    __shared__ int   s_best;
    __shared__ float s_lpmin;
    __shared__ int   s_alive[9];           // draws 0..8: hit still possible
    __shared__ float s_T[9];               // exact best-score per draw
    __shared__ uint32_t s_uthr[9];         // lenient raw-bits screens
    __shared__ float s_w9v[8];
    __shared__ int   s_w9i[8];

    const int b    = blockIdx.x;
    const int tid  = threadIdx.x;
    const int wid  = tid >> 5;
    const int lane = tid & 31;

    const uint32_t one = *(volatile uint32_t*)&g_one;   // opaque 1 for IMAD adds

    const float* xr = X + (size_t)b * (H_ALL * 3);

    const float w00 = W[0], w01 = W[1], w02 = W[2];
    const float w10 = W[3], w11 = W[4], w12 = W[5];
    const float w20 = W[6], w21 = W[7], w22 = W[8];
    const float bb0 = Bvec[0], bb1 = Bvec[1], bb2 = Bvec[2];

    // ---- logits + per-split max (splits: [0,2048), [2048,3072), [3072,4096))
    float lm0 = NEG_BIG, lm1 = NEG_BIG, lm2 = NEG_BIG;
#pragma unroll
    for (int j = 0; j < 16; j++) {
        const int h = tid + j * TPB;
        const float x0 = xr[3 * h + 0], x1 = xr[3 * h + 1], x2 = xr[3 * h + 2];
        float l;
        if (j < 8)       l = fmaf(x2, w02, fmaf(x1, w01, x0 * w00)) + bb0;
        else if (j < 12) l = fmaf(x2, w12, fmaf(x1, w11, x0 * w10)) + bb1;
        else             l = fmaf(x2, w22, fmaf(x1, w21, x0 * w20)) + bb2;
        sh[h] = l;
        if (j < 8)       lm0 = fmaxf(lm0, l);
        else if (j < 12) lm1 = fmaxf(lm1, l);
        else             lm2 = fmaxf(lm2, l);
    }
#pragma unroll
    for (int o = 16; o; o >>= 1) {
        lm0 = fmaxf(lm0, __shfl_xor_sync(0xffffffffu, lm0, o));
        lm1 = fmaxf(lm1, __shfl_xor_sync(0xffffffffu, lm1, o));
        lm2 = fmaxf(lm2, __shfl_xor_sync(0xffffffffu, lm2, o));
    }
    if (!lane) { s_red[0][wid] = lm0; s_red[1][wid] = lm1; s_red[2][wid] = lm2; }
    __syncthreads();
    if (tid < 3) {
        float m = s_red[tid][0];
#pragma unroll
        for (int k = 1; k < 8; k++) m = fmaxf(m, s_red[tid][k]);
        s_max[tid] = m;
    }
    __syncthreads();

    // ---- exp(l - max) and per-split sums
    const float m0 = s_max[0], m1 = s_max[1], m2 = s_max[2];
    float ls0 = 0.f, ls1 = 0.f, ls2 = 0.f;
#pragma unroll
    for (int j = 0; j < 16; j++) {
        const int h = tid + j * TPB;
        const float m = (j < 8) ? m0 : ((j < 12) ? m1 : m2);
        const float e = expf(sh[h] - m);
        sh[h] = e;
        if (j < 8) ls0 += e; else if (j < 12) ls1 += e; else ls2 += e;
    }
#pragma unroll
    for (int o = 16; o; o >>= 1) {
        ls0 += __shfl_xor_sync(0xffffffffu, ls0, o);
        ls1 += __shfl_xor_sync(0xffffffffu, ls1, o);
        ls2 += __shfl_xor_sync(0xffffffffu, ls2, o);
    }
    if (!lane) { s_red[0][wid] = ls0; s_red[1][wid] = ls1; s_red[2][wid] = ls2; }
    __syncthreads();
    if (tid < 3) {
        float s = s_red[tid][0];
#pragma unroll
        for (int k = 1; k < 8; k++) s += s_red[tid][k];
        s_sum[tid] = s;
    }
    __syncthreads();

    // ---- p = e/s into SMEM; best = argmax p; pmin for screen seeding
    const float su0 = s_sum[0], su1 = s_sum[1], su2 = s_sum[2];
    float bv = -1.0f; int bi = 0x7fffffff;
    float pmn = 3.0e38f;
#pragma unroll
    for (int j = 0; j < 16; j++) {
        const int h = tid + j * TPB;
        const float s = (j < 8) ? su0 : ((j < 12) ? su1 : su2);
        const float p = sh[h] / s;
        if (p > bv) { bv = p; bi = h; }
        pmn = fminf(pmn, p);
        sh[h] = p;                         // logf(p) deferred to use sites
    }

    // Upper bound on every logp (e <= 1 so p <= 1/su); +1e-5 covers div/log ULPs.
    const float lpmax =
        fmaxf(fmaxf(-logf(su0), -logf(su1)), -logf(su2)) + 1e-5f;

    // ---- block-reduce best + pmin
    warp_amax(bv, bi);
#pragma unroll
    for (int o = 16; o; o >>= 1)
        pmn = fminf(pmn, __shfl_xor_sync(0xffffffffu, pmn, o));
    if (!lane) { s_bv[wid] = bv; s_bi[wid] = bi; s_pm[wid] = pmn; }
    if (tid < 9) s_alive[tid] = 1;
    __syncthreads();
    if (tid == 0) {
        float v = s_bv[0]; int i = s_bi[0]; float pm = s_pm[0];
#pragma unroll
        for (int k = 1; k < 8; k++) {
            if (s_bv[k] > v || (s_bv[k] == v && s_bi[k] < i)) { v = s_bv[k]; i = s_bi[k]; }
            pm = fminf(pm, s_pm[k]);
        }
        s_best  = i;
        s_lpmin = logf(pm) - 1e-5f;        // true lower bound on all logp
    }
    __syncthreads();
    const int   best    = s_best;
    const float lpmin   = s_lpmin;
    const float lp_best = logf(sh[best]);
    const uint32_t cbase = ((uint32_t)b << 12);

    // ---- T_e = exact gumbel score of `best` in draw e, + fixed raw screens
    if (tid < 9) {
        const uint32_t mb =
            tf2x32_xor(cbase + (uint32_t)best + (uint32_t)tid * E_STRIDE, one) >> 9;
        const float T = gumbel_mbits(mb) + lp_best;   // identical fp path
        s_T[tid]    = T;
        s_uthr[tid] = screen_uthr(T, lpmax);
    }
    __syncthreads();

    // ---- warp-specialized early-kill scans for draws 0..8
    // warp w owns draw w; warp 0 also draw 8. 32-h chunks, ballot break.
    for (int e = wid; e < 9; e += 8) {
        const float T  = s_T[e];
        const uint32_t uth = s_uthr[e];
        const uint32_t ce = cbase + (uint32_t)e * E_STRIDE;
        bool killed = false;
#pragma unroll 1
        for (int k = 0; k < H_ALL / 32 && !killed; k++) {
            const int h = lane + k * 32;
            const uint32_t bits = tf2x32_xor(ce + (uint32_t)h, one);
            bool kill = false;
            if (bits >= uth) {                              // lenient screen
                const float v = gumbel_mbits(bits >> 9) + logf(sh[h]);
                kill = (v > T) || (v == T && h < best);     // exact verify
            }
            killed = (__ballot_sync(0xffffffffu, kill) != 0u);
        }
        if (killed && lane == 0) s_alive[e] = 0;
    }

    // ---- draw 9: screened running argmax (samples[-1]), ILP2, seeded screen
    float mv9 = NEG_BIG; int mi9 = 0;
    uint32_t uthr9 = 0u, tsrc9 = 0u;
    const uint32_t c9 = cbase + 9u * E_STRIDE;
#pragma unroll 1
    for (int j = 0; j < 8; j++) {
        const int h0 = tid + j * 512;
        const int h1 = h0 + 256;
        const uint32_t bits0 = tf2x32_xor(c9 + (uint32_t)h0, one);
        const uint32_t bits1 = tf2x32_xor(c9 + (uint32_t)h1, one);
        if (j == 0) {
            // seed the screen from warp-max raw bits (a true lower bound on
            // the final max: gumbel(wm)+lpmin <= that h's actual score <= max)
            const uint32_t wm = __reduce_max_sync(0xffffffffu,
                                                  bits0 > bits1 ? bits0 : bits1);
            uthr9 = screen_uthr(gumbel_mbits(wm >> 9) + lpmin, lpmax);
        }
        if (bits0 >= uthr9) {                               // lenient screen
            const float v = gumbel_mbits(bits0 >> 9) + logf(sh[h0]);
            if (v > mv9) { mv9 = v; mi9 = h0; }
        }
        if (bits1 >= uthr9) {
            const float v = gumbel_mbits(bits1 >> 9) + logf(sh[h1]);
            if (v > mv9) { mv9 = v; mi9 = h1; }
        }
        if (j < 7) {
            const uint32_t wm = __reduce_max_sync(0xffffffffu, fmap(mv9));
            if (wm > tsrc9) {                               // warp-uniform
                tsrc9 = wm;
                const uint32_t nt = screen_uthr(funmap(wm), lpmax);
                uthr9 = nt > uthr9 ? nt : uthr9;            // never loosen
            }
        }
    }

    // ---- block argmax for draw 9, then output
    warp_amax(mv9, mi9);
    if (!lane) { s_w9v[wid] = mv9; s_w9i[wid] = mi9; }
    __syncthreads();
    if (tid == 0) {
        float v = s_w9v[0]; int a9 = s_w9i[0];
#pragma unroll
        for (int k = 1; k < 8; k++) {
            if (s_w9v[k] > v || (s_w9v[k] == v && s_w9i[k] < a9)) { v = s_w9v[k]; a9 = s_w9i[k]; }
        }
        bool hit = (a9 == best);
#pragma unroll
        for (int e = 0; e < 9; e++) hit = hit || (s_alive[e] != 0);
        out[b] = (float)(hit ? best : a9);
    }
}

extern "C" void kernel_launch(void* const* d_in, const int* in_sizes, int n_in,
                              void* d_out, int out_size) {
    (void)in_sizes; (void)n_in; (void)out_size;
    const float* X = (const float*)d_in[0];
    const float* W = (const float*)d_in[1];
    const float* b = (const float*)d_in[2];
    rd_kernel<<<B_TOT, TPB>>>(X, W, b, (float*)d_out);
}